// round 4
// baseline (speedup 1.0000x reference)
#include <cuda_runtime.h>
#include <math.h>

#define Tdim 1653
#define Ddim 512
#define Bdim 2
#define Edim 8
#define DE 64
#define BE 16
#define BT (Bdim * Tdim)                  // 3306
#define TDE (Tdim * DE)                   // 105792
static const long long TT = (long long)Tdim * Tdim;   // 2732409

typedef unsigned long long u64;

// ------------------- packed f32x2 helpers ----------------------------------
__device__ __forceinline__ u64 pk2(float x, float y) {
    u64 r; asm("mov.b64 %0, {%1,%2};" : "=l"(r) : "f"(x), "f"(y)); return r;
}
__device__ __forceinline__ void fma2(u64 &d, u64 a, u64 b) {
    asm("fma.rn.f32x2 %0, %1, %2, %0;" : "+l"(d) : "l"(a), "l"(b));
}
__device__ __forceinline__ float2 up2(u64 v) {
    float2 r; asm("mov.b64 {%0,%1}, %2;" : "=f"(r.x), "=f"(r.y) : "l"(v)); return r;
}

// ------------------- scratch (static device allocations) -------------------
__device__ float g_Yq[BT * Ddim];
__device__ float g_Yk[BT * Ddim];
__device__ float g_Yv[BT * Ddim];
__device__ float g_Q [BE * TDE];          // per-head [T, 64]
__device__ float g_K [BE * TDE];          // per-head [T, 64]
__device__ float g_V [BE * TDE];          // per-head [T, 64]
__device__ float g_Wt[BE * TDE];          // per-head W^T: [64, T],  W = orth^T @ V
__device__ float g_S [(long long)BE * Tdim * Tdim];  // (Q K^T) * scale * punish
__device__ float g_O [BE * TDE];          // attention output [T, 64] per head
__device__ float g_X [BT * Ddim];         // reassembled [B,T,D]

struct Proj3 { const float* W[3]; const float* b[3]; float* Y[3]; };

// ------------------- packed NT GEMM core ------------------------------------
// C[M,N] = A[M,K] * B[N,K]^T ; BM=128, 256 threads, micro 8 x TN (TN even).
// As2 holds A values duplicated into both f32x2 lanes; Bs holds raw floats
// read back as u64 pairs (accumulator pairs run along n).
template <int BN, int TN>
__device__ __forceinline__ void gemm2_core(
    const float* __restrict__ A, const float* __restrict__ B,
    int M, int N, int K, int m0, int n0,
    u64 (&As2)[8][130], float (&Bs)[8][BN + 4], u64 (&acc)[8][TN / 2])
{
    const int tid = threadIdx.x;
    constexpr int NG = BN / TN;   // must be 16
    const int tx = tid % NG;
    const int ty = tid / NG;

#pragma unroll
    for (int i = 0; i < 8; ++i)
#pragma unroll
        for (int j = 0; j < TN / 2; ++j) acc[i][j] = 0ull;

    const int kIters = (K + 7) / 8;
    for (int kt = 0; kt < kIters; ++kt) {
        const int k0 = kt * 8;
        // A tile 128x8 -> duplicated u64
#pragma unroll
        for (int i = tid; i < 128 * 8; i += 256) {
            const int m = i >> 3, kk = i & 7;
            float v = (m0 + m < M && k0 + kk < K)
                      ? A[(long long)(m0 + m) * K + k0 + kk] : 0.f;
            As2[kk][m] = pk2(v, v);
        }
        // B tile BNx8 (float)
#pragma unroll
        for (int i = tid; i < BN * 8; i += 256) {
            const int n = i >> 3, kk = i & 7;
            Bs[kk][n] = (n0 + n < N && k0 + kk < K)
                        ? B[(long long)(n0 + n) * K + k0 + kk] : 0.f;
        }
        __syncthreads();
#pragma unroll
        for (int k = 0; k < 8; ++k) {
            u64 a2[8];
#pragma unroll
            for (int i = 0; i < 8; ++i) a2[i] = As2[k][ty * 8 + i];
            u64 b2[TN / 2];
            const u64* bp = reinterpret_cast<const u64*>(&Bs[k][tx * TN]);
#pragma unroll
            for (int j = 0; j < TN / 2; ++j) b2[j] = bp[j];
#pragma unroll
            for (int i = 0; i < 8; ++i)
#pragma unroll
                for (int j = 0; j < TN / 2; ++j)
                    fma2(acc[i][j], a2[i], b2[j]);
        }
        __syncthreads();
    }
}

// MODE 0: plain   MODE 1: +bias[n]   MODE 2: *scale*punish[m*T+n]
template <int BN, int TN, int MODE>
__global__ void __launch_bounds__(256, 2)
sgemm2_nt(const float* __restrict__ A, const float* __restrict__ B,
          float* __restrict__ C, int M, int N, int K,
          long long sA, long long sB, long long sC,
          const float* __restrict__ ep, float scale)
{
    const int bz = blockIdx.z;
    A += (long long)bz * sA;
    B += (long long)bz * sB;
    C += (long long)bz * sC;

    __shared__ __align__(16) u64   As2[8][130];
    __shared__ __align__(16) float Bs [8][BN + 4];

    const int m0 = blockIdx.y * 128;
    const int n0 = blockIdx.x * BN;
    const int tid = threadIdx.x;
    constexpr int NG = BN / TN;
    const int tx = tid % NG;
    const int ty = tid / NG;

    u64 acc[8][TN / 2];
    gemm2_core<BN, TN>(A, B, M, N, K, m0, n0, As2, Bs, acc);

#pragma unroll
    for (int i = 0; i < 8; ++i) {
        const int m = m0 + ty * 8 + i;
        if (m >= M) continue;
#pragma unroll
        for (int j = 0; j < TN / 2; ++j) {
            float2 v = up2(acc[i][j]);
            const int n = n0 + tx * TN + 2 * j;
            if (MODE == 1) {
                if (n < N)     v.x += ep[n];
                if (n + 1 < N) v.y += ep[n + 1];
            }
            if (MODE == 2) {
                if (n < N)     v.x *= scale * ep[(long long)m * Tdim + n];
                if (n + 1 < N) v.y *= scale * ep[(long long)m * Tdim + n + 1];
            }
            if (n < N)     C[(long long)m * N + n]     = v.x;
            if (n + 1 < N) C[(long long)m * N + n + 1] = v.y;
        }
    }
}

// Fused Q/K/V projections in one launch (z selects the weight set).
__global__ void __launch_bounds__(256, 2)
proj3_kernel(const float* __restrict__ X, Proj3 p)
{
    const int z = blockIdx.z;
    const float* W = p.W[z];
    const float* bias = p.b[z];
    float* Y = p.Y[z];

    __shared__ __align__(16) u64   As2[8][130];
    __shared__ __align__(16) float Bs [8][132];

    const int m0 = blockIdx.y * 128;
    const int n0 = blockIdx.x * 128;
    const int tid = threadIdx.x;
    const int tx = tid % 16;
    const int ty = tid / 16;

    u64 acc[8][4];
    gemm2_core<128, 8>(X, W, BT, Ddim, Ddim, m0, n0, As2, Bs, acc);

#pragma unroll
    for (int i = 0; i < 8; ++i) {
        const int m = m0 + ty * 8 + i;
        if (m >= BT) continue;
#pragma unroll
        for (int j = 0; j < 4; ++j) {
            float2 v = up2(acc[i][j]);
            const int n = n0 + tx * 8 + 2 * j;
            v.x += bias[n];
            v.y += bias[n + 1];
            Y[(long long)m * Ddim + n]     = v.x;
            Y[(long long)m * Ddim + n + 1] = v.y;
        }
    }
}

// ------------- W^T kernel:  Wt[d, t] = sum_s orth[s, t] * V[s, d] ----------
// per head. grid: (ceil(T/128), BE), 256 threads, micro 4(d) x 8(t) packed.
__global__ void __launch_bounds__(256, 2) wt_kernel(const float* __restrict__ orth)
{
    const int g = blockIdx.y;
    const float* V  = g_V  + (long long)g * TDE;      // [T, 64]
    const float* Og = orth + (long long)g * TT;       // [T, T]
    float* Wt = g_Wt + (long long)g * TDE;            // [64, T]

    __shared__ __align__(16) u64   Vs2[8][66];
    __shared__ __align__(16) float Os [8][132];

    const int n0 = blockIdx.x * 128;                  // t range
    const int tid = threadIdx.x;
    const int tx = tid & 15;                          // t group (x8)
    const int ty = tid >> 4;                          // d group (x4)

    u64 acc[4][4];
#pragma unroll
    for (int i = 0; i < 4; ++i)
#pragma unroll
        for (int j = 0; j < 4; ++j) acc[i][j] = 0ull;

    const int kIters = (Tdim + 7) / 8;
    for (int kt = 0; kt < kIters; ++kt) {
        const int s0 = kt * 8;
#pragma unroll
        for (int i = tid; i < 8 * 64; i += 256) {
            const int kk = i >> 6, d = i & 63;
            float v = (s0 + kk < Tdim) ? V[(long long)(s0 + kk) * DE + d] : 0.f;
            Vs2[kk][d] = pk2(v, v);
        }
#pragma unroll
        for (int i = tid; i < 8 * 128; i += 256) {
            const int kk = i >> 7, t = i & 127;
            Os[kk][t] = (s0 + kk < Tdim && n0 + t < Tdim)
                        ? Og[(long long)(s0 + kk) * Tdim + n0 + t] : 0.f;
        }
        __syncthreads();
#pragma unroll
        for (int k = 0; k < 8; ++k) {
            u64 a2[4];
#pragma unroll
            for (int i = 0; i < 4; ++i) a2[i] = Vs2[k][ty * 4 + i];
            u64 b2[4];
            const u64* bp = reinterpret_cast<const u64*>(&Os[k][tx * 8]);
#pragma unroll
            for (int j = 0; j < 4; ++j) b2[j] = bp[j];
#pragma unroll
            for (int i = 0; i < 4; ++i)
#pragma unroll
                for (int j = 0; j < 4; ++j)
                    fma2(acc[i][j], a2[i], b2[j]);
        }
        __syncthreads();
    }

#pragma unroll
    for (int i = 0; i < 4; ++i) {
        const int d = ty * 4 + i;
#pragma unroll
        for (int j = 0; j < 4; ++j) {
            float2 v = up2(acc[i][j]);
            const int t = n0 + tx * 8 + 2 * j;
            if (t < Tdim)     Wt[(long long)d * Tdim + t]     = v.x;
            if (t + 1 < Tdim) Wt[(long long)d * Tdim + t + 1] = v.y;
        }
    }
}

// ------------------- reshape / activation kernels --------------------------
__global__ void scatter_qkv_kernel()
{
    long long idx = (long long)blockIdx.x * 256 + threadIdx.x;
    const long long NTOT = (long long)BE * TDE;
    if (idx >= NTOT) return;
    const int g = (int)(idx / TDE);
    const int f = (int)(idx % TDE);
    const int b = g >> 3, e = g & 7;
    const int tt = f % Tdim;
    const int j  = f / Tdim;
    const long long src = ((long long)(b * Tdim + tt)) * Ddim + e * DE + j;

    g_Q[idx] = 1.2f / (1.f + expf(-1.6f * g_Yq[src]));
    g_K[idx] = 1.2f / (1.f + expf(-1.6f * g_Yk[src]));
    g_V[idx] = g_Yv[src];
}

__global__ void gather_x_kernel()
{
    const int idx = blockIdx.x * 256 + threadIdx.x;
    if (idx >= BT * Ddim) return;
    const int b   = idx / (Tdim * Ddim);
    const int rem = idx % (Tdim * Ddim);
    const int t = rem / Ddim, d = rem % Ddim;
    const int g = b * Edim + (d >> 6);
    g_X[idx] = g_O[((long long)g * Tdim + t) * DE + (d & 63)];
}

// ------------------- launch ------------------------------------------------
extern "C" void kernel_launch(void* const* d_in, const int* in_sizes, int n_in,
                              void* d_out, int out_size)
{
    const float* input  = (const float*)d_in[0];
    const float* Wq     = (const float*)d_in[1];
    const float* bq     = (const float*)d_in[2];
    const float* Wk     = (const float*)d_in[3];
    const float* bk     = (const float*)d_in[4];
    const float* Wv     = (const float*)d_in[5];
    const float* bv     = (const float*)d_in[6];
    const float* Wo     = (const float*)d_in[7];
    const float* bo     = (const float*)d_in[8];
    const float* punish = (const float*)d_in[9];
    const float* orth   = (const float*)d_in[10];
    float* out = (float*)d_out;

    float *Yq, *Yk, *Yv, *Q, *Kb, *S, *Wt, *O, *X;
    cudaGetSymbolAddress((void**)&Yq, g_Yq);
    cudaGetSymbolAddress((void**)&Yk, g_Yk);
    cudaGetSymbolAddress((void**)&Yv, g_Yv);
    cudaGetSymbolAddress((void**)&Q,  g_Q);
    cudaGetSymbolAddress((void**)&Kb, g_K);
    cudaGetSymbolAddress((void**)&S,  g_S);
    cudaGetSymbolAddress((void**)&Wt, g_Wt);
    cudaGetSymbolAddress((void**)&O,  g_O);
    cudaGetSymbolAddress((void**)&X,  g_X);

    const float inv_sqrt_T = 1.0f / sqrtf((float)Tdim);
    const dim3 blk(256);

    // 1) fused projections: Y = x @ W^T + b   [3306,512] x [512,512]^T  (z=3)
    {
        Proj3 p;
        p.W[0] = Wq; p.W[1] = Wk; p.W[2] = Wv;
        p.b[0] = bq; p.b[1] = bk; p.b[2] = bv;
        p.Y[0] = Yq; p.Y[1] = Yk; p.Y[2] = Yv;
        dim3 grid(512 / 128, (BT + 127) / 128, 3);
        proj3_kernel<<<grid, blk>>>(input, p);
    }

    // 2) reshape + sigmoid
    scatter_qkv_kernel<<<(BE * TDE + 255) / 256, blk>>>();

    // 3) W^T = (orth^T @ V)^T  per head
    {
        dim3 grid((Tdim + 127) / 128, BE, 1);
        wt_kernel<<<grid, blk>>>(orth);
    }

    // 4) S = (Q K^T) * (1/sqrt(T)) * punish    batched [1653,64]x[1653,64]^T
    {
        dim3 grid((Tdim + 127) / 128, (Tdim + 127) / 128, BE);
        sgemm2_nt<128, 8, 2><<<grid, blk>>>(Q, Kb, S, Tdim, Tdim, DE,
                                            (long long)TDE, (long long)TDE, TT,
                                            punish, inv_sqrt_T);
    }

    // 5) O = S @ W   == NT gemm against Wt[64, T]   batched [1653,1653]x[64,1653]^T
    {
        dim3 grid(1, (Tdim + 127) / 128, BE);
        sgemm2_nt<64, 4, 0><<<grid, blk>>>(S, Wt, O, Tdim, DE, Tdim,
                                           TT, (long long)TDE, (long long)TDE,
                                           nullptr, 0.f);
    }

    // 6) inverse reshape
    gather_x_kernel<<<(BT * Ddim + 255) / 256, blk>>>();

    // 7) final projection: out = X @ Wo^T + bo
    {
        dim3 grid(512 / 128, (BT + 127) / 128, 1);
        sgemm2_nt<128, 8, 1><<<grid, blk>>>(X, Wo, out, BT, Ddim, Ddim, 0, 0, 0, bo, 0.f);
    }
}

// round 5
// speedup vs baseline: 1.0001x; 1.0001x over previous
#include <cuda_runtime.h>
#include <math.h>

#define Tdim 1653
#define Ddim 512
#define Bdim 2
#define Edim 8
#define DE 64
#define BE 16
#define BT (Bdim * Tdim)                  // 3306
#define TDE (Tdim * DE)                   // 105792
static const long long TT = (long long)Tdim * Tdim;   // 2732409

typedef unsigned long long u64;

// ------------------- packed f32x2 helpers ----------------------------------
__device__ __forceinline__ u64 pk2(float x, float y) {
    u64 r; asm("mov.b64 %0, {%1,%2};" : "=l"(r) : "f"(x), "f"(y)); return r;
}
__device__ __forceinline__ void fma2(u64 &d, u64 a, u64 b) {
    asm("fma.rn.f32x2 %0, %1, %2, %0;" : "+l"(d) : "l"(a), "l"(b));
}
__device__ __forceinline__ float2 up2(u64 v) {
    float2 r; asm("mov.b64 {%0,%1}, %2;" : "=f"(r.x), "=f"(r.y) : "l"(v)); return r;
}

// ------------------- scratch (static device allocations) -------------------
__device__ float g_Yq[BT * Ddim];
__device__ float g_Yk[BT * Ddim];
__device__ float g_Yv[BT * Ddim];
__device__ float g_Q [BE * TDE];          // per-head [T, 64]
__device__ float g_K [BE * TDE];          // per-head [T, 64]
__device__ float g_V [BE * TDE];          // per-head [T, 64]
__device__ float g_Wt[BE * TDE];          // per-head W^T: [64, T],  W = orth^T @ V
__device__ float g_S [(long long)BE * Tdim * Tdim];  // (Q K^T) * scale * punish
__device__ float g_O [BE * TDE];          // attention output [T, 64] per head
__device__ float g_X [BT * Ddim];         // reassembled [B,T,D]

struct Proj3 { const float* W[3]; const float* b[3]; float* Y[3]; };

// ------------------- packed NT GEMM core ------------------------------------
// C[M,N] = A[M,K] * B[N,K]^T ; BM=128, 256 threads, micro 8 x TN (TN even).
// As2 holds A values duplicated into both f32x2 lanes; Bs holds raw floats
// read back as u64 pairs (accumulator pairs run along n).
template <int BN, int TN>
__device__ __forceinline__ void gemm2_core(
    const float* __restrict__ A, const float* __restrict__ B,
    int M, int N, int K, int m0, int n0,
    u64 (&As2)[8][130], float (&Bs)[8][BN + 4], u64 (&acc)[8][TN / 2])
{
    const int tid = threadIdx.x;
    constexpr int NG = BN / TN;   // must be 16
    const int tx = tid % NG;
    const int ty = tid / NG;

#pragma unroll
    for (int i = 0; i < 8; ++i)
#pragma unroll
        for (int j = 0; j < TN / 2; ++j) acc[i][j] = 0ull;

    const int kIters = (K + 7) / 8;
    for (int kt = 0; kt < kIters; ++kt) {
        const int k0 = kt * 8;
        // A tile 128x8 -> duplicated u64
#pragma unroll
        for (int i = tid; i < 128 * 8; i += 256) {
            const int m = i >> 3, kk = i & 7;
            float v = (m0 + m < M && k0 + kk < K)
                      ? A[(long long)(m0 + m) * K + k0 + kk] : 0.f;
            As2[kk][m] = pk2(v, v);
        }
        // B tile BNx8 (float)
#pragma unroll
        for (int i = tid; i < BN * 8; i += 256) {
            const int n = i >> 3, kk = i & 7;
            Bs[kk][n] = (n0 + n < N && k0 + kk < K)
                        ? B[(long long)(n0 + n) * K + k0 + kk] : 0.f;
        }
        __syncthreads();
#pragma unroll
        for (int k = 0; k < 8; ++k) {
            u64 a2[8];
#pragma unroll
            for (int i = 0; i < 8; ++i) a2[i] = As2[k][ty * 8 + i];
            u64 b2[TN / 2];
            const u64* bp = reinterpret_cast<const u64*>(&Bs[k][tx * TN]);
#pragma unroll
            for (int j = 0; j < TN / 2; ++j) b2[j] = bp[j];
#pragma unroll
            for (int i = 0; i < 8; ++i)
#pragma unroll
                for (int j = 0; j < TN / 2; ++j)
                    fma2(acc[i][j], a2[i], b2[j]);
        }
        __syncthreads();
    }
}

// MODE 0: plain   MODE 1: +bias[n]   MODE 2: *scale*punish[m*T+n]
template <int BN, int TN, int MODE>
__global__ void __launch_bounds__(256, 2)
sgemm2_nt(const float* __restrict__ A, const float* __restrict__ B,
          float* __restrict__ C, int M, int N, int K,
          long long sA, long long sB, long long sC,
          const float* __restrict__ ep, float scale)
{
    const int bz = blockIdx.z;
    A += (long long)bz * sA;
    B += (long long)bz * sB;
    C += (long long)bz * sC;

    __shared__ __align__(16) u64   As2[8][130];
    __shared__ __align__(16) float Bs [8][BN + 4];

    const int m0 = blockIdx.y * 128;
    const int n0 = blockIdx.x * BN;
    const int tid = threadIdx.x;
    constexpr int NG = BN / TN;
    const int tx = tid % NG;
    const int ty = tid / NG;

    u64 acc[8][TN / 2];
    gemm2_core<BN, TN>(A, B, M, N, K, m0, n0, As2, Bs, acc);

#pragma unroll
    for (int i = 0; i < 8; ++i) {
        const int m = m0 + ty * 8 + i;
        if (m >= M) continue;
#pragma unroll
        for (int j = 0; j < TN / 2; ++j) {
            float2 v = up2(acc[i][j]);
            const int n = n0 + tx * TN + 2 * j;
            if (MODE == 1) {
                if (n < N)     v.x += ep[n];
                if (n + 1 < N) v.y += ep[n + 1];
            }
            if (MODE == 2) {
                if (n < N)     v.x *= scale * ep[(long long)m * Tdim + n];
                if (n + 1 < N) v.y *= scale * ep[(long long)m * Tdim + n + 1];
            }
            if (n < N)     C[(long long)m * N + n]     = v.x;
            if (n + 1 < N) C[(long long)m * N + n + 1] = v.y;
        }
    }
}

// Fused Q/K/V projections in one launch (z selects the weight set).
__global__ void __launch_bounds__(256, 2)
proj3_kernel(const float* __restrict__ X, Proj3 p)
{
    const int z = blockIdx.z;
    const float* W = p.W[z];
    const float* bias = p.b[z];
    float* Y = p.Y[z];

    __shared__ __align__(16) u64   As2[8][130];
    __shared__ __align__(16) float Bs [8][132];

    const int m0 = blockIdx.y * 128;
    const int n0 = blockIdx.x * 128;
    const int tid = threadIdx.x;
    const int tx = tid % 16;
    const int ty = tid / 16;

    u64 acc[8][4];
    gemm2_core<128, 8>(X, W, BT, Ddim, Ddim, m0, n0, As2, Bs, acc);

#pragma unroll
    for (int i = 0; i < 8; ++i) {
        const int m = m0 + ty * 8 + i;
        if (m >= BT) continue;
#pragma unroll
        for (int j = 0; j < 4; ++j) {
            float2 v = up2(acc[i][j]);
            const int n = n0 + tx * 8 + 2 * j;
            v.x += bias[n];
            v.y += bias[n + 1];
            Y[(long long)m * Ddim + n]     = v.x;
            Y[(long long)m * Ddim + n + 1] = v.y;
        }
    }
}

// ------------- W^T kernel:  Wt[d, t] = sum_s orth[s, t] * V[s, d] ----------
// per head. grid: (ceil(T/128), BE), 256 threads, micro 4(d) x 8(t) packed.
__global__ void __launch_bounds__(256, 2) wt_kernel(const float* __restrict__ orth)
{
    const int g = blockIdx.y;
    const float* V  = g_V  + (long long)g * TDE;      // [T, 64]
    const float* Og = orth + (long long)g * TT;       // [T, T]
    float* Wt = g_Wt + (long long)g * TDE;            // [64, T]

    __shared__ __align__(16) u64   Vs2[8][66];
    __shared__ __align__(16) float Os [8][132];

    const int n0 = blockIdx.x * 128;                  // t range
    const int tid = threadIdx.x;
    const int tx = tid & 15;                          // t group (x8)
    const int ty = tid >> 4;                          // d group (x4)

    u64 acc[4][4];
#pragma unroll
    for (int i = 0; i < 4; ++i)
#pragma unroll
        for (int j = 0; j < 4; ++j) acc[i][j] = 0ull;

    const int kIters = (Tdim + 7) / 8;
    for (int kt = 0; kt < kIters; ++kt) {
        const int s0 = kt * 8;
#pragma unroll
        for (int i = tid; i < 8 * 64; i += 256) {
            const int kk = i >> 6, d = i & 63;
            float v = (s0 + kk < Tdim) ? V[(long long)(s0 + kk) * DE + d] : 0.f;
            Vs2[kk][d] = pk2(v, v);
        }
#pragma unroll
        for (int i = tid; i < 8 * 128; i += 256) {
            const int kk = i >> 7, t = i & 127;
            Os[kk][t] = (s0 + kk < Tdim && n0 + t < Tdim)
                        ? Og[(long long)(s0 + kk) * Tdim + n0 + t] : 0.f;
        }
        __syncthreads();
#pragma unroll
        for (int k = 0; k < 8; ++k) {
            u64 a2[4];
#pragma unroll
            for (int i = 0; i < 4; ++i) a2[i] = Vs2[k][ty * 4 + i];
            u64 b2[4];
            const u64* bp = reinterpret_cast<const u64*>(&Os[k][tx * 8]);
#pragma unroll
            for (int j = 0; j < 4; ++j) b2[j] = bp[j];
#pragma unroll
            for (int i = 0; i < 4; ++i)
#pragma unroll
                for (int j = 0; j < 4; ++j)
                    fma2(acc[i][j], a2[i], b2[j]);
        }
        __syncthreads();
    }

#pragma unroll
    for (int i = 0; i < 4; ++i) {
        const int d = ty * 4 + i;
#pragma unroll
        for (int j = 0; j < 4; ++j) {
            float2 v = up2(acc[i][j]);
            const int t = n0 + tx * 8 + 2 * j;
            if (t < Tdim)     Wt[(long long)d * Tdim + t]     = v.x;
            if (t + 1 < Tdim) Wt[(long long)d * Tdim + t + 1] = v.y;
        }
    }
}

// ------------------- reshape / activation kernels --------------------------
__global__ void scatter_qkv_kernel()
{
    long long idx = (long long)blockIdx.x * 256 + threadIdx.x;
    const long long NTOT = (long long)BE * TDE;
    if (idx >= NTOT) return;
    const int g = (int)(idx / TDE);
    const int f = (int)(idx % TDE);
    const int b = g >> 3, e = g & 7;
    const int tt = f % Tdim;
    const int j  = f / Tdim;
    const long long src = ((long long)(b * Tdim + tt)) * Ddim + e * DE + j;

    g_Q[idx] = 1.2f / (1.f + expf(-1.6f * g_Yq[src]));
    g_K[idx] = 1.2f / (1.f + expf(-1.6f * g_Yk[src]));
    g_V[idx] = g_Yv[src];
}

__global__ void gather_x_kernel()
{
    const int idx = blockIdx.x * 256 + threadIdx.x;
    if (idx >= BT * Ddim) return;
    const int b   = idx / (Tdim * Ddim);
    const int rem = idx % (Tdim * Ddim);
    const int t = rem / Ddim, d = rem % Ddim;
    const int g = b * Edim + (d >> 6);
    g_X[idx] = g_O[((long long)g * Tdim + t) * DE + (d & 63)];
}

// ------------------- launch ------------------------------------------------
extern "C" void kernel_launch(void* const* d_in, const int* in_sizes, int n_in,
                              void* d_out, int out_size)
{
    const float* input  = (const float*)d_in[0];
    const float* Wq     = (const float*)d_in[1];
    const float* bq     = (const float*)d_in[2];
    const float* Wk     = (const float*)d_in[3];
    const float* bk     = (const float*)d_in[4];
    const float* Wv     = (const float*)d_in[5];
    const float* bv     = (const float*)d_in[6];
    const float* Wo     = (const float*)d_in[7];
    const float* bo     = (const float*)d_in[8];
    const float* punish = (const float*)d_in[9];
    const float* orth   = (const float*)d_in[10];
    float* out = (float*)d_out;

    float *Yq, *Yk, *Yv, *Q, *Kb, *S, *Wt, *O, *X;
    cudaGetSymbolAddress((void**)&Yq, g_Yq);
    cudaGetSymbolAddress((void**)&Yk, g_Yk);
    cudaGetSymbolAddress((void**)&Yv, g_Yv);
    cudaGetSymbolAddress((void**)&Q,  g_Q);
    cudaGetSymbolAddress((void**)&Kb, g_K);
    cudaGetSymbolAddress((void**)&S,  g_S);
    cudaGetSymbolAddress((void**)&Wt, g_Wt);
    cudaGetSymbolAddress((void**)&O,  g_O);
    cudaGetSymbolAddress((void**)&X,  g_X);

    const float inv_sqrt_T = 1.0f / sqrtf((float)Tdim);
    const dim3 blk(256);

    // 1) fused projections: Y = x @ W^T + b   [3306,512] x [512,512]^T  (z=3)
    {
        Proj3 p;
        p.W[0] = Wq; p.W[1] = Wk; p.W[2] = Wv;
        p.b[0] = bq; p.b[1] = bk; p.b[2] = bv;
        p.Y[0] = Yq; p.Y[1] = Yk; p.Y[2] = Yv;
        dim3 grid(512 / 128, (BT + 127) / 128, 3);
        proj3_kernel<<<grid, blk>>>(input, p);
    }

    // 2) reshape + sigmoid
    scatter_qkv_kernel<<<(BE * TDE + 255) / 256, blk>>>();

    // 3) W^T = (orth^T @ V)^T  per head
    {
        dim3 grid((Tdim + 127) / 128, BE, 1);
        wt_kernel<<<grid, blk>>>(orth);
    }

    // 4) S = (Q K^T) * (1/sqrt(T)) * punish    batched [1653,64]x[1653,64]^T
    {
        dim3 grid((Tdim + 127) / 128, (Tdim + 127) / 128, BE);
        sgemm2_nt<128, 8, 2><<<grid, blk>>>(Q, Kb, S, Tdim, Tdim, DE,
                                            (long long)TDE, (long long)TDE, TT,
                                            punish, inv_sqrt_T);
    }

    // 5) O = S @ W   == NT gemm against Wt[64, T]   batched [1653,1653]x[64,1653]^T
    {
        dim3 grid(1, (Tdim + 127) / 128, BE);
        sgemm2_nt<64, 4, 0><<<grid, blk>>>(S, Wt, O, Tdim, DE, Tdim,
                                           TT, (long long)TDE, (long long)TDE,
                                           nullptr, 0.f);
    }

    // 6) inverse reshape
    gather_x_kernel<<<(BT * Ddim + 255) / 256, blk>>>();

    // 7) final projection: out = X @ Wo^T + bo
    {
        dim3 grid(512 / 128, (BT + 127) / 128, 1);
        sgemm2_nt<128, 8, 1><<<grid, blk>>>(X, Wo, out, BT, Ddim, Ddim, 0, 0, 0, bo, 0.f);
    }
}

// round 6
// speedup vs baseline: 1.0028x; 1.0027x over previous
#include <cuda_runtime.h>
#include <math.h>

#define Tdim 1653
#define Ddim 512
#define Bdim 2
#define Edim 8
#define DE 64
#define BE 16
#define BT (Bdim * Tdim)                  // 3306
#define TDE (Tdim * DE)                   // 105792
static const long long TT = (long long)Tdim * Tdim;   // 2732409

typedef unsigned long long u64;

// ------------------- packed f32x2 helpers ----------------------------------
__device__ __forceinline__ u64 pk2(float x, float y) {
    u64 r; asm("mov.b64 %0, {%1,%2};" : "=l"(r) : "f"(x), "f"(y)); return r;
}
__device__ __forceinline__ void fma2(u64 &d, u64 a, u64 b) {
    asm("fma.rn.f32x2 %0, %1, %2, %0;" : "+l"(d) : "l"(a), "l"(b));
}
__device__ __forceinline__ float2 up2(u64 v) {
    float2 r; asm("mov.b64 {%0,%1}, %2;" : "=f"(r.x), "=f"(r.y) : "l"(v)); return r;
}

// ------------------- scratch (static device allocations) -------------------
__device__ float g_Yq[BT * Ddim];
__device__ float g_Yk[BT * Ddim];
__device__ float g_Yv[BT * Ddim];
__device__ float g_Q [BE * TDE];          // per-head [T, 64]
__device__ float g_K [BE * TDE];          // per-head [T, 64]
__device__ float g_V [BE * TDE];          // per-head [T, 64]
__device__ float g_Wt[BE * TDE];          // per-head W^T: [64, T],  W = orth^T @ V
__device__ float g_S [(long long)BE * Tdim * Tdim];  // (Q K^T) * scale * punish
__device__ float g_O [BE * TDE];          // attention output [T, 64] per head
__device__ float g_X [BT * Ddim];         // reassembled [B,T,D]

struct Proj3 { const float* W[3]; const float* b[3]; float* Y[3]; };

// ------------------- packed NT GEMM core ------------------------------------
// C[M,N] = A[M,K] * B[N,K]^T ; BM=128, 256 threads, micro 8 x TN (TN even).
// As2 holds A values duplicated into both f32x2 lanes; Bs holds raw floats
// read back as u64 pairs (accumulator pairs run along n).
template <int BN, int TN>
__device__ __forceinline__ void gemm2_core(
    const float* __restrict__ A, const float* __restrict__ B,
    int M, int N, int K, int m0, int n0,
    u64 (&As2)[8][130], float (&Bs)[8][BN + 4], u64 (&acc)[8][TN / 2])
{
    const int tid = threadIdx.x;
    constexpr int NG = BN / TN;   // must be 16
    const int tx = tid % NG;
    const int ty = tid / NG;

#pragma unroll
    for (int i = 0; i < 8; ++i)
#pragma unroll
        for (int j = 0; j < TN / 2; ++j) acc[i][j] = 0ull;

    const int kIters = (K + 7) / 8;
    for (int kt = 0; kt < kIters; ++kt) {
        const int k0 = kt * 8;
        // A tile 128x8 -> duplicated u64
#pragma unroll
        for (int i = tid; i < 128 * 8; i += 256) {
            const int m = i >> 3, kk = i & 7;
            float v = (m0 + m < M && k0 + kk < K)
                      ? A[(long long)(m0 + m) * K + k0 + kk] : 0.f;
            As2[kk][m] = pk2(v, v);
        }
        // B tile BNx8 (float)
#pragma unroll
        for (int i = tid; i < BN * 8; i += 256) {
            const int n = i >> 3, kk = i & 7;
            Bs[kk][n] = (n0 + n < N && k0 + kk < K)
                        ? B[(long long)(n0 + n) * K + k0 + kk] : 0.f;
        }
        __syncthreads();
#pragma unroll
        for (int k = 0; k < 8; ++k) {
            u64 a2[8];
#pragma unroll
            for (int i = 0; i < 8; ++i) a2[i] = As2[k][ty * 8 + i];
            u64 b2[TN / 2];
            const u64* bp = reinterpret_cast<const u64*>(&Bs[k][tx * TN]);
#pragma unroll
            for (int j = 0; j < TN / 2; ++j) b2[j] = bp[j];
#pragma unroll
            for (int i = 0; i < 8; ++i)
#pragma unroll
                for (int j = 0; j < TN / 2; ++j)
                    fma2(acc[i][j], a2[i], b2[j]);
        }
        __syncthreads();
    }
}

// MODE 0: plain   MODE 1: +bias[n]   MODE 2: *scale*punish[m*T+n]
template <int BN, int TN, int MODE>
__global__ void __launch_bounds__(256, 2)
sgemm2_nt(const float* __restrict__ A, const float* __restrict__ B,
          float* __restrict__ C, int M, int N, int K,
          long long sA, long long sB, long long sC,
          const float* __restrict__ ep, float scale)
{
    const int bz = blockIdx.z;
    A += (long long)bz * sA;
    B += (long long)bz * sB;
    C += (long long)bz * sC;

    __shared__ __align__(16) u64   As2[8][130];
    __shared__ __align__(16) float Bs [8][BN + 4];

    const int m0 = blockIdx.y * 128;
    const int n0 = blockIdx.x * BN;
    const int tid = threadIdx.x;
    constexpr int NG = BN / TN;
    const int tx = tid % NG;
    const int ty = tid / NG;

    u64 acc[8][TN / 2];
    gemm2_core<BN, TN>(A, B, M, N, K, m0, n0, As2, Bs, acc);

#pragma unroll
    for (int i = 0; i < 8; ++i) {
        const int m = m0 + ty * 8 + i;
        if (m >= M) continue;
#pragma unroll
        for (int j = 0; j < TN / 2; ++j) {
            float2 v = up2(acc[i][j]);
            const int n = n0 + tx * TN + 2 * j;
            if (MODE == 1) {
                if (n < N)     v.x += ep[n];
                if (n + 1 < N) v.y += ep[n + 1];
            }
            if (MODE == 2) {
                if (n < N)     v.x *= scale * ep[(long long)m * Tdim + n];
                if (n + 1 < N) v.y *= scale * ep[(long long)m * Tdim + n + 1];
            }
            if (n < N)     C[(long long)m * N + n]     = v.x;
            if (n + 1 < N) C[(long long)m * N + n + 1] = v.y;
        }
    }
}

// Fused Q/K/V projections in one launch (z selects the weight set).
__global__ void __launch_bounds__(256, 2)
proj3_kernel(const float* __restrict__ X, Proj3 p)
{
    const int z = blockIdx.z;
    const float* W = p.W[z];
    const float* bias = p.b[z];
    float* Y = p.Y[z];

    __shared__ __align__(16) u64   As2[8][130];
    __shared__ __align__(16) float Bs [8][132];

    const int m0 = blockIdx.y * 128;
    const int n0 = blockIdx.x * 128;
    const int tid = threadIdx.x;
    const int tx = tid % 16;
    const int ty = tid / 16;

    u64 acc[8][4];
    gemm2_core<128, 8>(X, W, BT, Ddim, Ddim, m0, n0, As2, Bs, acc);

#pragma unroll
    for (int i = 0; i < 8; ++i) {
        const int m = m0 + ty * 8 + i;
        if (m >= BT) continue;
#pragma unroll
        for (int j = 0; j < 4; ++j) {
            float2 v = up2(acc[i][j]);
            const int n = n0 + tx * 8 + 2 * j;
            v.x += bias[n];
            v.y += bias[n + 1];
            Y[(long long)m * Ddim + n]     = v.x;
            Y[(long long)m * Ddim + n + 1] = v.y;
        }
    }
}

// ------------- W^T kernel:  Wt[d, t] = sum_s orth[s, t] * V[s, d] ----------
// per head. grid: (ceil(T/128), BE), 256 threads, micro 4(d) x 8(t) packed.
__global__ void __launch_bounds__(256, 2) wt_kernel(const float* __restrict__ orth)
{
    const int g = blockIdx.y;
    const float* V  = g_V  + (long long)g * TDE;      // [T, 64]
    const float* Og = orth + (long long)g * TT;       // [T, T]
    float* Wt = g_Wt + (long long)g * TDE;            // [64, T]

    __shared__ __align__(16) u64   Vs2[8][66];
    __shared__ __align__(16) float Os [8][132];

    const int n0 = blockIdx.x * 128;                  // t range
    const int tid = threadIdx.x;
    const int tx = tid & 15;                          // t group (x8)
    const int ty = tid >> 4;                          // d group (x4)

    u64 acc[4][4];
#pragma unroll
    for (int i = 0; i < 4; ++i)
#pragma unroll
        for (int j = 0; j < 4; ++j) acc[i][j] = 0ull;

    const int kIters = (Tdim + 7) / 8;
    for (int kt = 0; kt < kIters; ++kt) {
        const int s0 = kt * 8;
#pragma unroll
        for (int i = tid; i < 8 * 64; i += 256) {
            const int kk = i >> 6, d = i & 63;
            float v = (s0 + kk < Tdim) ? V[(long long)(s0 + kk) * DE + d] : 0.f;
            Vs2[kk][d] = pk2(v, v);
        }
#pragma unroll
        for (int i = tid; i < 8 * 128; i += 256) {
            const int kk = i >> 7, t = i & 127;
            Os[kk][t] = (s0 + kk < Tdim && n0 + t < Tdim)
                        ? Og[(long long)(s0 + kk) * Tdim + n0 + t] : 0.f;
        }
        __syncthreads();
#pragma unroll
        for (int k = 0; k < 8; ++k) {
            u64 a2[4];
#pragma unroll
            for (int i = 0; i < 4; ++i) a2[i] = Vs2[k][ty * 4 + i];
            u64 b2[4];
            const u64* bp = reinterpret_cast<const u64*>(&Os[k][tx * 8]);
#pragma unroll
            for (int j = 0; j < 4; ++j) b2[j] = bp[j];
#pragma unroll
            for (int i = 0; i < 4; ++i)
#pragma unroll
                for (int j = 0; j < 4; ++j)
                    fma2(acc[i][j], a2[i], b2[j]);
        }
        __syncthreads();
    }

#pragma unroll
    for (int i = 0; i < 4; ++i) {
        const int d = ty * 4 + i;
#pragma unroll
        for (int j = 0; j < 4; ++j) {
            float2 v = up2(acc[i][j]);
            const int t = n0 + tx * 8 + 2 * j;
            if (t < Tdim)     Wt[(long long)d * Tdim + t]     = v.x;
            if (t + 1 < Tdim) Wt[(long long)d * Tdim + t + 1] = v.y;
        }
    }
}

// ------------------- reshape / activation kernels --------------------------
__global__ void scatter_qkv_kernel()
{
    long long idx = (long long)blockIdx.x * 256 + threadIdx.x;
    const long long NTOT = (long long)BE * TDE;
    if (idx >= NTOT) return;
    const int g = (int)(idx / TDE);
    const int f = (int)(idx % TDE);
    const int b = g >> 3, e = g & 7;
    const int tt = f % Tdim;
    const int j  = f / Tdim;
    const long long src = ((long long)(b * Tdim + tt)) * Ddim + e * DE + j;

    g_Q[idx] = 1.2f / (1.f + expf(-1.6f * g_Yq[src]));
    g_K[idx] = 1.2f / (1.f + expf(-1.6f * g_Yk[src]));
    g_V[idx] = g_Yv[src];
}

__global__ void gather_x_kernel()
{
    const int idx = blockIdx.x * 256 + threadIdx.x;
    if (idx >= BT * Ddim) return;
    const int b   = idx / (Tdim * Ddim);
    const int rem = idx % (Tdim * Ddim);
    const int t = rem / Ddim, d = rem % Ddim;
    const int g = b * Edim + (d >> 6);
    g_X[idx] = g_O[((long long)g * Tdim + t) * DE + (d & 63)];
}

// ------------------- launch ------------------------------------------------
extern "C" void kernel_launch(void* const* d_in, const int* in_sizes, int n_in,
                              void* d_out, int out_size)
{
    const float* input  = (const float*)d_in[0];
    const float* Wq     = (const float*)d_in[1];
    const float* bq     = (const float*)d_in[2];
    const float* Wk     = (const float*)d_in[3];
    const float* bk     = (const float*)d_in[4];
    const float* Wv     = (const float*)d_in[5];
    const float* bv     = (const float*)d_in[6];
    const float* Wo     = (const float*)d_in[7];
    const float* bo     = (const float*)d_in[8];
    const float* punish = (const float*)d_in[9];
    const float* orth   = (const float*)d_in[10];
    float* out = (float*)d_out;

    float *Yq, *Yk, *Yv, *Q, *Kb, *S, *Wt, *O, *X;
    cudaGetSymbolAddress((void**)&Yq, g_Yq);
    cudaGetSymbolAddress((void**)&Yk, g_Yk);
    cudaGetSymbolAddress((void**)&Yv, g_Yv);
    cudaGetSymbolAddress((void**)&Q,  g_Q);
    cudaGetSymbolAddress((void**)&Kb, g_K);
    cudaGetSymbolAddress((void**)&S,  g_S);
    cudaGetSymbolAddress((void**)&Wt, g_Wt);
    cudaGetSymbolAddress((void**)&O,  g_O);
    cudaGetSymbolAddress((void**)&X,  g_X);

    const float inv_sqrt_T = 1.0f / sqrtf((float)Tdim);
    const dim3 blk(256);

    // 1) fused projections: Y = x @ W^T + b   [3306,512] x [512,512]^T  (z=3)
    {
        Proj3 p;
        p.W[0] = Wq; p.W[1] = Wk; p.W[2] = Wv;
        p.b[0] = bq; p.b[1] = bk; p.b[2] = bv;
        p.Y[0] = Yq; p.Y[1] = Yk; p.Y[2] = Yv;
        dim3 grid(512 / 128, (BT + 127) / 128, 3);
        proj3_kernel<<<grid, blk>>>(input, p);
    }

    // 2) reshape + sigmoid
    scatter_qkv_kernel<<<(BE * TDE + 255) / 256, blk>>>();

    // 3) W^T = (orth^T @ V)^T  per head
    {
        dim3 grid((Tdim + 127) / 128, BE, 1);
        wt_kernel<<<grid, blk>>>(orth);
    }

    // 4) S = (Q K^T) * (1/sqrt(T)) * punish    batched [1653,64]x[1653,64]^T
    {
        dim3 grid((Tdim + 127) / 128, (Tdim + 127) / 128, BE);
        sgemm2_nt<128, 8, 2><<<grid, blk>>>(Q, Kb, S, Tdim, Tdim, DE,
                                            (long long)TDE, (long long)TDE, TT,
                                            punish, inv_sqrt_T);
    }

    // 5) O = S @ W   == NT gemm against Wt[64, T]   batched [1653,1653]x[64,1653]^T
    {
        dim3 grid(1, (Tdim + 127) / 128, BE);
        sgemm2_nt<64, 4, 0><<<grid, blk>>>(S, Wt, O, Tdim, DE, Tdim,
                                           TT, (long long)TDE, (long long)TDE,
                                           nullptr, 0.f);
    }

    // 6) inverse reshape
    gather_x_kernel<<<(BT * Ddim + 255) / 256, blk>>>();

    // 7) final projection: out = X @ Wo^T + bo
    {
        dim3 grid(512 / 128, (BT + 127) / 128, 1);
        sgemm2_nt<128, 8, 1><<<grid, blk>>>(X, Wo, out, BT, Ddim, Ddim, 0, 0, 0, bo, 0.f);
    }
}

// round 9
// speedup vs baseline: 2.2738x; 2.2674x over previous
#include <cuda_runtime.h>
#include <cuda_bf16.h>
#include <math.h>
#include <stdint.h>

#define Tdim 1653
#define TSP  1664                      // padded S row stride (mult of 16 floats)
#define Ddim 512
#define Bdim 2
#define Edim 8
#define DE 64
#define BE 16
#define BT 3306
#define TDE (Tdim * DE)
typedef __nv_bfloat16 bf16;
static const long long TT = (long long)Tdim * Tdim;

// ------------------- device scratch (fp32 everywhere) ------------------------
__device__ float g_Y[3 * BT * Ddim];
__device__ float g_Wcat[3 * Ddim * Ddim];
__device__ float g_bcat[3 * Ddim];
__device__ float g_Q[BE * TDE], g_K[BE * TDE], g_V[BE * TDE];
__device__ float g_W2[BE * TDE];                        // W = orth^T @ V, [T,64]/head
__device__ float g_S[(long long)BE * Tdim * TSP];       // (QK^T)*scale*punish, padded
__device__ float g_O[BE * TDE];
__device__ float g_X[BT * Ddim];

// ------------------- helpers -------------------------------------------------
__device__ __forceinline__ uint32_t smem_u32(const void* p) {
    uint32_t a;
    asm("{ .reg .u64 t; cvta.to.shared.u64 t, %1; cvt.u32.u64 %0, t; }"
        : "=r"(a) : "l"(p));
    return a;
}
__device__ __forceinline__ void sp2(float v, bf16& h, bf16& l) {
    h = __float2bfloat16(v);
    l = __float2bfloat16(v - __bfloat162float(h));
}
__device__ __forceinline__ void ldm4(uint32_t* r, uint32_t a) {
    asm volatile("ldmatrix.sync.aligned.m8n8.x4.shared.b16 {%0,%1,%2,%3}, [%4];"
        : "=r"(r[0]), "=r"(r[1]), "=r"(r[2]), "=r"(r[3]) : "r"(a));
}
__device__ __forceinline__ void ldm4t(uint32_t* r, uint32_t a) {
    asm volatile("ldmatrix.sync.aligned.m8n8.x4.trans.shared.b16 {%0,%1,%2,%3}, [%4];"
        : "=r"(r[0]), "=r"(r[1]), "=r"(r[2]), "=r"(r[3]) : "r"(a));
}
__device__ __forceinline__ void mma16816(float* d, const uint32_t* a, const uint32_t* b) {
    asm volatile("mma.sync.aligned.m16n8k16.row.col.f32.bf16.bf16.f32 "
        "{%0,%1,%2,%3}, {%4,%5,%6,%7}, {%8,%9}, {%0,%1,%2,%3};"
        : "+f"(d[0]), "+f"(d[1]), "+f"(d[2]), "+f"(d[3])
        : "r"(a[0]), "r"(a[1]), "r"(a[2]), "r"(a[3]), "r"(b[0]), "r"(b[1]));
}

__device__ __forceinline__ void cvt16(const float* __restrict__ s, bf16* hp, bf16* lp)
{
#pragma unroll
    for (int q = 0; q < 4; ++q) {
        float4 f = *reinterpret_cast<const float4*>(s + q * 4);
        bf16 h0, l0, h1, l1, h2, l2, h3, l3;
        sp2(f.x, h0, l0); sp2(f.y, h1, l1);
        sp2(f.z, h2, l2); sp2(f.w, h3, l3);
        __nv_bfloat162 a, b;
        a.x = h0; a.y = h1; b.x = h2; b.y = h3;
        reinterpret_cast<__nv_bfloat162*>(hp)[q * 2]     = a;
        reinterpret_cast<__nv_bfloat162*>(hp)[q * 2 + 1] = b;
        a.x = l0; a.y = l1; b.x = l2; b.y = l3;
        reinterpret_cast<__nv_bfloat162*>(lp)[q * 2]     = a;
        reinterpret_cast<__nv_bfloat162*>(lp)[q * 2 + 1] = b;
    }
}

// ---- tile loaders: fp32 gmem -> bf16 hi/lo smem ----
// no-trans: 128 rows x 32 k, src[r][k] pitch ld, smem pitch 40
__device__ __forceinline__ void ld_nt(const float* __restrict__ src, int r0, int Rtot,
                                      int ld, int k0, int K, bf16* H, bf16* L)
{
    const int t = threadIdx.x;
    const int r = t >> 1, h = t & 1;
    const int kb = k0 + h * 16;
    bf16* hp = H + r * 40 + h * 16;
    bf16* lp = L + r * 40 + h * 16;
    const bool rowok = (r0 + r) < Rtot;
    const float* s = src + (long long)(r0 + r) * ld + kb;
    if (rowok && kb + 16 <= K && ((reinterpret_cast<uintptr_t>(s) & 15u) == 0)) {
        cvt16(s, hp, lp);
    } else {
#pragma unroll
        for (int q = 0; q < 16; ++q) {
            float v = (rowok && kb + q < K) ? s[q] : 0.f;
            sp2(v, hp[q], lp[q]);
        }
    }
}

// trans: 32 k-rows x C cols, src[k][c] pitch ld, smem pitch C+8
template <int C>
__device__ __forceinline__ void ld_tr(const float* __restrict__ src, int k0, int K,
                                      int c0, int Ctot, int ld, bf16* H, bf16* L)
{
    constexpr int P  = C + 8;
    constexpr int CH = C / 16;
    const int t = threadIdx.x;
    if (t >= 32 * CH) return;
    const int kr = t / CH, mc = (t % CH) * 16;
    const bool rowok = (k0 + kr) < K;
    const float* s = src + (long long)(k0 + kr) * ld + c0 + mc;
    bf16* hp = H + kr * P + mc;
    bf16* lp = L + kr * P + mc;
    if (rowok && c0 + mc + 16 <= Ctot && ((reinterpret_cast<uintptr_t>(s) & 15u) == 0)) {
        cvt16(s, hp, lp);
    } else {
#pragma unroll
        for (int q = 0; q < 16; ++q) {
            float v = (rowok && c0 + mc + q < Ctot) ? s[q] : 0.f;
            sp2(v, hp[q], lp[q]);
        }
    }
}

// ------------------- split-bf16 tensor-core GEMM -----------------------------
// C[M,N] = A[M,K]*B^T (logical). TRA: A stored [k][m]; TRB: B stored [k][n].
// MODE 0: plain  1: +bias ep[n]  2: *scale*ep[m*N+n] (punish, stride N)
template <int BN, int TRA, int TRB, int MODE>
__global__ void __launch_bounds__(256)
mma_gemm(const float* __restrict__ A, const float* __restrict__ B,
         float* __restrict__ C, int M, int N, int K,
         int lda, int ldb, int ldc,
         long long sA, long long sB, long long sC,
         const float* __restrict__ ep, long long sEp, float scale)
{
    constexpr int PA  = TRA ? 136 : 40;
    constexpr int PB  = TRB ? (BN + 8) : 40;
    constexpr int ASZ = TRA ? 32 * 136 : 128 * 40;
    constexpr int BSZ = TRB ? 32 * (BN + 8) : BN * 40;
    __shared__ bf16 Ah[ASZ], Al[ASZ], Bh[BSZ], Bl[BSZ];

    const int bz = blockIdx.z;
    A += (long long)bz * sA;
    B += (long long)bz * sB;
    C += (long long)bz * sC;
    if (MODE > 0) ep += (long long)bz * sEp;

    const int m0 = blockIdx.y * 128, n0 = blockIdx.x * BN;
    const int tid = threadIdx.x, l = tid & 31, wid = tid >> 5;
    constexpr int WN = BN / 2;      // 64 or 32
    constexpr int NT = WN / 8;      // 8 or 4
    const int wm = wid & 3, wn = wid >> 2;
    const int rmw = wm * 32;
    const int nbw = wn * WN;

    float acc[2][NT][4];
#pragma unroll
    for (int i = 0; i < 2; ++i)
#pragma unroll
        for (int j = 0; j < NT; ++j)
#pragma unroll
            for (int q = 0; q < 4; ++q) acc[i][j][q] = 0.f;

    const uint32_t baseAh = smem_u32(Ah), baseAl = smem_u32(Al);
    const uint32_t baseBh = smem_u32(Bh), baseBl = smem_u32(Bl);
    uint32_t aoff, boff;
    if (TRA) aoff = (((l & 7) + ((l >> 4) << 3)) * PA + ((l >> 3) & 1) * 8) * 2;
    else     aoff = ((l & 15) * PA + (l >> 4) * 8) * 2;
    if (TRB) boff = (((l & 7) + (((l >> 3) & 1) << 3)) * PB + ((l >> 4) << 3)) * 2;
    else     boff = (((l & 7) + ((l >> 4) << 3)) * PB + ((l >> 3) & 1) * 8) * 2;

    const int kIters = (K + 31) / 32;
    for (int kt = 0; kt < kIters; ++kt) {
        const int k0 = kt * 32;
        if (TRA) ld_tr<128>(A, k0, K, m0, M, lda, Ah, Al);
        else     ld_nt(A, m0, M, lda, k0, K, Ah, Al);
        if (TRB) ld_tr<BN>(B, k0, K, n0, N, ldb, Bh, Bl);
        else     ld_nt(B, n0, N, ldb, k0, K, Bh, Bl);
        __syncthreads();
#pragma unroll
        for (int ks = 0; ks < 2; ++ks) {
            uint32_t ah[2][4], al2[2][4];
#pragma unroll
            for (int mt = 0; mt < 2; ++mt) {
                const int rm = rmw + mt * 16;
                const uint32_t rel = TRA ? (uint32_t)((ks * 16 * PA + rm) * 2)
                                         : (uint32_t)((rm * PA + ks * 16) * 2);
                if (TRA) { ldm4t(ah[mt], baseAh + rel + aoff); ldm4t(al2[mt], baseAl + rel + aoff); }
                else     { ldm4 (ah[mt], baseAh + rel + aoff); ldm4 (al2[mt], baseAl + rel + aoff); }
            }
            uint32_t bh[NT][2], bl2[NT][2];
#pragma unroll
            for (int np = 0; np < NT / 2; ++np) {
                const int nb = nbw + np * 16;
                const uint32_t rel = TRB ? (uint32_t)((ks * 16 * PB + nb) * 2)
                                         : (uint32_t)((nb * PB + ks * 16) * 2);
                uint32_t rh[4], rl[4];
                if (TRB) { ldm4t(rh, baseBh + rel + boff); ldm4t(rl, baseBl + rel + boff); }
                else     { ldm4 (rh, baseBh + rel + boff); ldm4 (rl, baseBl + rel + boff); }
                bh[2 * np][0] = rh[0]; bh[2 * np][1] = rh[1];
                bh[2 * np + 1][0] = rh[2]; bh[2 * np + 1][1] = rh[3];
                bl2[2 * np][0] = rl[0]; bl2[2 * np][1] = rl[1];
                bl2[2 * np + 1][0] = rl[2]; bl2[2 * np + 1][1] = rl[3];
            }
#pragma unroll
            for (int mt = 0; mt < 2; ++mt)
#pragma unroll
                for (int nt = 0; nt < NT; ++nt) {
                    mma16816(acc[mt][nt], ah[mt],  bh[nt]);
                    mma16816(acc[mt][nt], ah[mt],  bl2[nt]);
                    mma16816(acc[mt][nt], al2[mt], bh[nt]);
                }
        }
        __syncthreads();
    }

    // epilogue
#pragma unroll
    for (int mt = 0; mt < 2; ++mt)
#pragma unroll
        for (int nt = 0; nt < NT; ++nt)
#pragma unroll
            for (int half = 0; half < 2; ++half) {
                const int m = m0 + rmw + mt * 16 + (l >> 2) + half * 8;
                const int n = n0 + nbw + nt * 8 + (l & 3) * 2;
                if (m >= M) continue;
                float v0 = acc[mt][nt][half * 2 + 0];
                float v1 = acc[mt][nt][half * 2 + 1];
                if (MODE == 1) {
                    if (n < N)     v0 += ep[n];
                    if (n + 1 < N) v1 += ep[n + 1];
                }
                if (MODE == 2) {
                    if (n < N)     v0 *= scale * ep[(long long)m * N + n];
                    if (n + 1 < N) v1 *= scale * ep[(long long)m * N + n + 1];
                }
                if (n + 1 < N) {
                    *reinterpret_cast<float2*>(C + (long long)m * ldc + n) = make_float2(v0, v1);
                } else if (n < N) {
                    C[(long long)m * ldc + n] = v0;
                }
            }
}

// ------------------- elementwise kernels -------------------------------------
__global__ void pack_wb(const float* Wq, const float* Wk, const float* Wv,
                        const float* bq, const float* bk, const float* bv)
{
    const int i = blockIdx.x * 256 + threadIdx.x;
    const int WW = Ddim * Ddim;
    if (i < WW) {
        g_Wcat[i] = Wq[i];
        g_Wcat[WW + i] = Wk[i];
        g_Wcat[2 * WW + i] = Wv[i];
    }
    if (i < Ddim) {
        g_bcat[i] = bq[i];
        g_bcat[Ddim + i] = bk[i];
        g_bcat[2 * Ddim + i] = bv[i];
    }
}

__global__ void scatter_qkv()
{
    const int idx = blockIdx.x * 256 + threadIdx.x;
    if (idx >= BE * TDE) return;
    const int g = idx / TDE, f = idx % TDE;
    const int b = g >> 3, e = g & 7;
    const int tt = f % Tdim, j = f / Tdim;
    const long long src = (long long)(b * Tdim + tt) * Ddim + e * DE + j;
    const float yq = g_Y[src];
    const float yk = g_Y[(long long)BT * Ddim + src];
    const float yv = g_Y[2ll * BT * Ddim + src];
    g_Q[idx] = 1.2f / (1.f + expf(-1.6f * yq));
    g_K[idx] = 1.2f / (1.f + expf(-1.6f * yk));
    g_V[idx] = yv;
}

__global__ void gather_x()
{
    const int idx = blockIdx.x * 256 + threadIdx.x;
    if (idx >= BT * Ddim) return;
    const int b = idx / (Tdim * Ddim);
    const int rem = idx % (Tdim * Ddim);
    const int t = rem / Ddim, d = rem % Ddim;
    const int g = b * Edim + (d >> 6);
    g_X[idx] = g_O[((long long)g * Tdim + t) * DE + (d & 63)];
}

// ------------------- launch --------------------------------------------------
extern "C" void kernel_launch(void* const* d_in, const int* in_sizes, int n_in,
                              void* d_out, int out_size)
{
    const float* input  = (const float*)d_in[0];
    const float* Wq     = (const float*)d_in[1];
    const float* bq     = (const float*)d_in[2];
    const float* Wk     = (const float*)d_in[3];
    const float* bk     = (const float*)d_in[4];
    const float* Wv     = (const float*)d_in[5];
    const float* bv     = (const float*)d_in[6];
    const float* Wo     = (const float*)d_in[7];
    const float* bo     = (const float*)d_in[8];
    const float* punish = (const float*)d_in[9];
    const float* orth   = (const float*)d_in[10];
    float* out = (float*)d_out;

    float *Y, *Wcat, *bcat, *Q, *Kp, *V, *W2, *S, *O, *X;
    cudaGetSymbolAddress((void**)&Y,    g_Y);
    cudaGetSymbolAddress((void**)&Wcat, g_Wcat);
    cudaGetSymbolAddress((void**)&bcat, g_bcat);
    cudaGetSymbolAddress((void**)&Q,    g_Q);
    cudaGetSymbolAddress((void**)&Kp,   g_K);
    cudaGetSymbolAddress((void**)&V,    g_V);
    cudaGetSymbolAddress((void**)&W2,   g_W2);
    cudaGetSymbolAddress((void**)&S,    g_S);
    cudaGetSymbolAddress((void**)&O,    g_O);
    cudaGetSymbolAddress((void**)&X,    g_X);

    const float inv_sqrt_T = 1.0f / sqrtf((float)Tdim);
    const int WW = Ddim * Ddim;

    // 0) pack Q/K/V weights for one fused launch
    pack_wb<<<(WW + 255) / 256, 256>>>(Wq, Wk, Wv, bq, bk, bv);

    // 1) projections: Y[z] = input @ W[z]^T + b[z]
    mma_gemm<128, 0, 0, 1><<<dim3(4, 26, 3), 256>>>(
        input, Wcat, Y, BT, Ddim, Ddim, Ddim, Ddim, Ddim,
        0ll, (long long)WW, (long long)BT * Ddim, bcat, (long long)Ddim, 0.f);

    // 2) reshape + sigmoid
    scatter_qkv<<<(BE * TDE + 255) / 256, 256>>>();

    // 3) W2 = orth^T @ V  per head  (A=orth [s][t] trans, B=V [s][d] trans)
    mma_gemm<64, 1, 1, 0><<<dim3(1, 13, BE), 256>>>(
        orth, V, W2, Tdim, DE, Tdim, Tdim, DE, DE,
        TT, (long long)TDE, (long long)TDE, nullptr, 0ll, 0.f);

    // 4) S = (Q K^T) * scale * punish  (stored with padded stride TSP)
    mma_gemm<128, 0, 0, 2><<<dim3(13, 13, BE), 256>>>(
        Q, Kp, S, Tdim, Tdim, DE, DE, DE, TSP,
        (long long)TDE, (long long)TDE, (long long)Tdim * TSP, punish, 0ll, inv_sqrt_T);

    // 5) O = S @ W2  (A=S no-trans lda=TSP, B=W2 [s][d] trans)
    mma_gemm<64, 0, 1, 0><<<dim3(1, 13, BE), 256>>>(
        S, W2, O, Tdim, DE, Tdim, TSP, DE, DE,
        (long long)Tdim * TSP, (long long)TDE, (long long)TDE, nullptr, 0ll, 0.f);

    // 6) inverse reshape
    gather_x<<<(BT * Ddim + 255) / 256, 256>>>();

    // 7) out = X @ Wo^T + bo
    mma_gemm<128, 0, 0, 1><<<dim3(4, 26, 1), 256>>>(
        X, Wo, out, BT, Ddim, Ddim, Ddim, Ddim, Ddim,
        0ll, 0ll, 0ll, bo, 0ll, 0.f);
}